// round 3
// baseline (speedup 1.0000x reference)
#include <cuda_runtime.h>
#include <cuda_bf16.h>

#define D_MODEL 768
#define KP_MODEL 384            // D/2 (u32 pairs)
#define N_HEADS 12
#define HD      64
#define B_SZ    4
#define T_SEQ   2048
#define M_TOK   (B_SZ * T_SEQ)  // 8192
#define N_QKV   (3 * D_MODEL)   // 2304

// ---------------- static device scratch (hi/lo bf16-pair planes, u32) -------
__device__ unsigned g_xh[(size_t)M_TOK * KP_MODEL],  g_xl[(size_t)M_TOK * KP_MODEL];
__device__ unsigned g_wqh[(size_t)KP_MODEL * N_QKV], g_wql[(size_t)KP_MODEL * N_QKV];
__device__ unsigned g_woh[(size_t)KP_MODEL * D_MODEL], g_wol[(size_t)KP_MODEL * D_MODEL];
// head-major [B][H][T][32] pair planes
#define HM_SZ ((size_t)B_SZ * N_HEADS * T_SEQ * 32)
__device__ unsigned g_qh[HM_SZ], g_ql[HM_SZ];
__device__ unsigned g_kh[HM_SZ], g_kl[HM_SZ];
__device__ unsigned g_vh[HM_SZ], g_vl[HM_SZ];
// attention output planes (A-operand layout for out-proj)
__device__ unsigned g_ah[(size_t)M_TOK * KP_MODEL], g_al[(size_t)M_TOK * KP_MODEL];

// ---------------------------------------------------------------------------
__device__ __forceinline__ void mma_bf16(float c[4], const unsigned a[4],
                                         unsigned b0, unsigned b1)
{
    asm volatile(
        "mma.sync.aligned.m16n8k16.row.col.f32.bf16.bf16.f32 "
        "{%0,%1,%2,%3}, {%4,%5,%6,%7}, {%8,%9}, {%0,%1,%2,%3};\n"
        : "+f"(c[0]), "+f"(c[1]), "+f"(c[2]), "+f"(c[3])
        : "r"(a[0]), "r"(a[1]), "r"(a[2]), "r"(a[3]), "r"(b0), "r"(b1));
}

__device__ __forceinline__ unsigned pack_bf2(float e_lo, float e_hi)
{
    __nv_bfloat162 t = __floats2bfloat162_rn(e_lo, e_hi); // .x -> low half
    return *reinterpret_cast<unsigned*>(&t);
}

__device__ __forceinline__ void split2(float x0, float x1, unsigned& hi, unsigned& lo)
{
    float h0 = __bfloat162float(__float2bfloat16(x0));
    float h1 = __bfloat162float(__float2bfloat16(x1));
    hi = pack_bf2(h0, h1);
    lo = pack_bf2(x0 - h0, x1 - h1);
}

__device__ __forceinline__ void cp16(unsigned* dst_smem, const unsigned* src)
{
    unsigned saddr = (unsigned)__cvta_generic_to_shared(dst_smem);
    asm volatile("cp.async.cg.shared.global [%0], [%1], 16;\n" :: "r"(saddr), "l"(src));
}
__device__ __forceinline__ void cp_commit() { asm volatile("cp.async.commit_group;\n"); }
template <int N>
__device__ __forceinline__ void cp_wait() { asm volatile("cp.async.wait_group %0;\n" :: "n"(N)); }

// ---------------------------------------------------------------------------
// Split kernels (run once per launch; memory-bound, tiny)
// ---------------------------------------------------------------------------
__global__ void split_rowpairs(const float* __restrict__ src,
                               unsigned* __restrict__ H, unsigned* __restrict__ L,
                               int total)
{
    int i = blockIdx.x * blockDim.x + threadIdx.x;
    if (i < total) {
        float2 v = ((const float2*)src)[i];
        unsigned h, l;
        split2(v.x, v.y, h, l);
        H[i] = h; L[i] = l;
    }
}

// Pack pairs along K across two rows of W[K][N] -> planes [K/2][N]
__global__ void split_colpairs(const float* __restrict__ src,
                               unsigned* __restrict__ H, unsigned* __restrict__ L,
                               int N, int total)
{
    int i = blockIdx.x * blockDim.x + threadIdx.x;
    if (i < total) {
        int kp = i / N, n = i - kp * N;
        float a = src[(size_t)(2 * kp) * N + n];
        float b = src[(size_t)(2 * kp + 1) * N + n];
        unsigned h, l;
        split2(a, b, h, l);
        H[i] = h; L[i] = l;
    }
}

// ---------------------------------------------------------------------------
// GEMM on pre-split planes. C[M,N] = A @ B (+bias).
// 256 thr = 8 warps (4x2), tile 128x128, BK=32 (16 pairs), cp.async dbl-buffer.
// EPI=0: fp32 C out. EPI=1: QKV epilogue -> head-major split planes.
// ---------------------------------------------------------------------------
#define GA_STR 20
#define GB_STR 136
#define GA_SZ  (128 * GA_STR)      // 2560 u32
#define GB_SZ  (16 * GB_STR)       // 2176 u32
#define GBUF   (2 * GA_SZ + 2 * GB_SZ)  // 9472 u32
#define GEMM_SMEM (2 * GBUF * 4)   // 75776 bytes

template <int EPI>
__global__ __launch_bounds__(256) void gemm_planes(
    const unsigned* __restrict__ Ah, const unsigned* __restrict__ Al,
    const unsigned* __restrict__ Bh, const unsigned* __restrict__ Bl,
    const float* __restrict__ bias, float* __restrict__ Cout,
    int M, int N, int K)
{
    extern __shared__ unsigned sm[];
    const int tid  = threadIdx.x;
    const int lane = tid & 31;
    const int wid  = tid >> 5;
    const int wm   = wid >> 1;
    const int wn   = wid & 1;
    const int lq   = lane >> 2;
    const int lr   = lane & 3;
    const int bm = blockIdx.y, bn = blockIdx.x;
    const int KP = K >> 1;

    float acc[2][8][4];
#pragma unroll
    for (int mt = 0; mt < 2; mt++)
#pragma unroll
        for (int n = 0; n < 8; n++)
#pragma unroll
            for (int j = 0; j < 4; j++) acc[mt][n][j] = 0.0f;

    auto load_tile = [&](int kt, int buf) {
        unsigned* AHs = sm + buf * GBUF;
        unsigned* ALs = AHs + GA_SZ;
        unsigned* BHs = ALs + GA_SZ;
        unsigned* BLs = BHs + GB_SZ;
        const int kp0 = kt * 16;
#pragma unroll
        for (int i = 0; i < 2; i++) {
            int idx = tid + i * 256;          // 512 chunks: 128 rows x 4
            int row = idx >> 2, c4 = (idx & 3) * 4;
            size_t g = (size_t)(bm * 128 + row) * KP + kp0 + c4;
            cp16(&AHs[row * GA_STR + c4], Ah + g);
            cp16(&ALs[row * GA_STR + c4], Al + g);
        }
#pragma unroll
        for (int i = 0; i < 2; i++) {
            int idx = tid + i * 256;          // 512 chunks: 16 rows x 32
            int row = idx >> 5, c4 = (idx & 31) * 4;
            size_t g = (size_t)(kp0 + row) * N + bn * 128 + c4;
            cp16(&BHs[row * GB_STR + c4], Bh + g);
            cp16(&BLs[row * GB_STR + c4], Bl + g);
        }
    };

    const int KT = K / 32;
    load_tile(0, 0);
    cp_commit();

    for (int kt = 0; kt < KT; kt++) {
        int buf = kt & 1;
        if (kt + 1 < KT) {
            load_tile(kt + 1, buf ^ 1);
            cp_commit();
            cp_wait<1>();
        } else {
            cp_wait<0>();
        }
        __syncthreads();

        unsigned* AHs = sm + buf * GBUF;
        unsigned* ALs = AHs + GA_SZ;
        unsigned* BHs = ALs + GA_SZ;
        unsigned* BLs = BHs + GB_SZ;

#pragma unroll
        for (int kk = 0; kk < 2; kk++) {
            unsigned ah[2][4], al[2][4];
#pragma unroll
            for (int mt = 0; mt < 2; mt++) {
                int r = wm * 32 + mt * 16 + lq;
                int p = kk * 8 + lr;
                ah[mt][0] = AHs[r * GA_STR + p];
                ah[mt][1] = AHs[(r + 8) * GA_STR + p];
                ah[mt][2] = AHs[r * GA_STR + p + 4];
                ah[mt][3] = AHs[(r + 8) * GA_STR + p + 4];
                al[mt][0] = ALs[r * GA_STR + p];
                al[mt][1] = ALs[(r + 8) * GA_STR + p];
                al[mt][2] = ALs[r * GA_STR + p + 4];
                al[mt][3] = ALs[(r + 8) * GA_STR + p + 4];
            }
#pragma unroll
            for (int n = 0; n < 8; n++) {
                int col = wn * 64 + n * 8 + lq;
                unsigned bh0 = BHs[(kk * 8 + lr) * GB_STR + col];
                unsigned bh1 = BHs[(kk * 8 + lr + 4) * GB_STR + col];
                unsigned bl0 = BLs[(kk * 8 + lr) * GB_STR + col];
                unsigned bl1 = BLs[(kk * 8 + lr + 4) * GB_STR + col];
#pragma unroll
                for (int mt = 0; mt < 2; mt++) {
                    mma_bf16(acc[mt][n], ah[mt], bh0, bh1);
                    mma_bf16(acc[mt][n], ah[mt], bl0, bl1);
                    mma_bf16(acc[mt][n], al[mt], bh0, bh1);
                }
            }
        }
        __syncthreads();
    }

    // ---- epilogue
#pragma unroll
    for (int mt = 0; mt < 2; mt++) {
        int row0 = bm * 128 + wm * 32 + mt * 16 + lq;
#pragma unroll
        for (int n = 0; n < 8; n++) {
            int col = bn * 128 + wn * 64 + n * 8 + 2 * lr;
            float b0 = bias[col], b1 = bias[col + 1];
            float x0 = acc[mt][n][0] + b0, x1 = acc[mt][n][1] + b1;
            float y0 = acc[mt][n][2] + b0, y1 = acc[mt][n][3] + b1;
            if (EPI == 0) {
                *(float2*)&Cout[(size_t)row0 * N + col]       = make_float2(x0, x1);
                *(float2*)&Cout[(size_t)(row0 + 8) * N + col] = make_float2(y0, y1);
            } else {
                int seg = col / D_MODEL;
                int nn  = col - seg * D_MODEL;
                int h   = nn >> 6;
                int dp  = (nn & 63) >> 1;
                if (seg == 0) { x0 *= 0.125f; x1 *= 0.125f; y0 *= 0.125f; y1 *= 0.125f; }
                unsigned* H = (seg == 0) ? g_qh : (seg == 1) ? g_kh : g_vh;
                unsigned* L = (seg == 0) ? g_ql : (seg == 1) ? g_kl : g_vl;
                int bb = row0 >> 11, t = row0 & 2047;
                size_t o = ((size_t)(bb * N_HEADS + h) * T_SEQ + t) * 32 + dp;
                unsigned hh, ll;
                split2(x0, x1, hh, ll);
                H[o] = hh; L[o] = ll;
                split2(y0, y1, hh, ll);
                H[o + 8 * 32] = hh; L[o + 8 * 32] = ll;
            }
        }
    }
}

// ---------------------------------------------------------------------------
// Flash attention (causal), split-bf16 tensor cores, pre-split inputs.
// Block = 128 thr (4 warps), 64-query tile of one (b,h).
// Smem (u32): KH/KL [64][36], VH/VL [32][72], PH/PL [64][36]
// ---------------------------------------------------------------------------
#define AT_SK 36
#define AT_SV 72
#define ATTN_SMEM ((2 * 64 * AT_SK + 2 * 32 * AT_SV + 2 * 64 * AT_SK) * 4)

__global__ __launch_bounds__(128) void attn_tc()
{
    extern __shared__ unsigned usm[];
    unsigned* KH = usm;
    unsigned* KL = usm + 64 * AT_SK;
    unsigned* VH = usm + 2 * 64 * AT_SK;
    unsigned* VL = VH + 32 * AT_SV;
    unsigned* PH = VL + 32 * AT_SV;
    unsigned* PL = PH + 64 * AT_SK;

    const int b = blockIdx.z, h = blockIdx.y;
    const int qt = gridDim.x - 1 - blockIdx.x;      // heavy tiles first
    const int tid = threadIdx.x;
    const int w = tid >> 5, lane = tid & 31;
    const int lq = lane >> 2, lr = lane & 3;
    const size_t bh_base = (size_t)(b * N_HEADS + h) * T_SEQ * 32;

    // ---- Q fragments straight from global planes (Q pre-scaled)
    unsigned qh[4][4], ql[4][4];
    {
        const unsigned* Qh = g_qh + bh_base + (size_t)qt * 64 * 32;
        const unsigned* Ql = g_ql + bh_base + (size_t)qt * 64 * 32;
        int r0 = w * 16 + lq;
#pragma unroll
        for (int kk = 0; kk < 4; kk++) {
            int p = kk * 8 + lr;
            qh[kk][0] = Qh[r0 * 32 + p];
            qh[kk][1] = Qh[(r0 + 8) * 32 + p];
            qh[kk][2] = Qh[r0 * 32 + p + 4];
            qh[kk][3] = Qh[(r0 + 8) * 32 + p + 4];
            ql[kk][0] = Ql[r0 * 32 + p];
            ql[kk][1] = Ql[(r0 + 8) * 32 + p];
            ql[kk][2] = Ql[r0 * 32 + p + 4];
            ql[kk][3] = Ql[(r0 + 8) * 32 + p + 4];
        }
    }

    float o_acc[8][4];
#pragma unroll
    for (int n = 0; n < 8; n++)
#pragma unroll
        for (int j = 0; j < 4; j++) o_acc[n][j] = 0.0f;
    float m0 = -1e30f, m1 = -1e30f, l0 = 0.0f, l1 = 0.0f;

    for (int kt = 0; kt <= qt; kt++) {
        __syncthreads();
        // K tile: contiguous 2048-u32 block per plane -> cp.async raw copy
        {
            const unsigned* Kgh = g_kh + bh_base + (size_t)kt * 64 * 32;
            const unsigned* Kgl = g_kl + bh_base + (size_t)kt * 64 * 32;
#pragma unroll
            for (int i = 0; i < 4; i++) {
                int idx = tid + i * 128;          // 512 chunks: 64 rows x 8
                int row = idx >> 3, c4 = (idx & 7) * 4;
                cp16(&KH[row * AT_SK + c4], Kgh + row * 32 + c4);
                cp16(&KL[row * AT_SK + c4], Kgl + row * 32 + c4);
            }
            cp_commit();
        }
        // V tile: repack d-pairs -> key-pairs with PRMT (overlaps K cp.async)
        {
            const unsigned* Vgh = g_vh + bh_base + (size_t)kt * 64 * 32;
            const unsigned* Vgl = g_vl + bh_base + (size_t)kt * 64 * 32;
#pragma unroll
            for (int i = 0; i < 2; i++) {
                int idx = tid + i * 128;          // 256: 32 kp x 8 jb
                int kp = idx >> 3, jb = (idx & 7) * 4;
                uint4 a = *(const uint4*)(Vgh + (2 * kp) * 32 + jb);
                uint4 c = *(const uint4*)(Vgh + (2 * kp + 1) * 32 + jb);
                uint4 o0, o1;
                o0.x = __byte_perm(a.x, c.x, 0x5410); o0.y = __byte_perm(a.x, c.x, 0x7632);
                o0.z = __byte_perm(a.y, c.y, 0x5410); o0.w = __byte_perm(a.y, c.y, 0x7632);
                o1.x = __byte_perm(a.z, c.z, 0x5410); o1.y = __byte_perm(a.z, c.z, 0x7632);
                o1.z = __byte_perm(a.w, c.w, 0x5410); o1.w = __byte_perm(a.w, c.w, 0x7632);
                *(uint4*)&VH[kp * AT_SV + 2 * jb]     = o0;
                *(uint4*)&VH[kp * AT_SV + 2 * jb + 4] = o1;
                a = *(const uint4*)(Vgl + (2 * kp) * 32 + jb);
                c = *(const uint4*)(Vgl + (2 * kp + 1) * 32 + jb);
                o0.x = __byte_perm(a.x, c.x, 0x5410); o0.y = __byte_perm(a.x, c.x, 0x7632);
                o0.z = __byte_perm(a.y, c.y, 0x5410); o0.w = __byte_perm(a.y, c.y, 0x7632);
                o1.x = __byte_perm(a.z, c.z, 0x5410); o1.y = __byte_perm(a.z, c.z, 0x7632);
                o1.z = __byte_perm(a.w, c.w, 0x5410); o1.w = __byte_perm(a.w, c.w, 0x7632);
                *(uint4*)&VL[kp * AT_SV + 2 * jb]     = o0;
                *(uint4*)&VL[kp * AT_SV + 2 * jb + 4] = o1;
            }
        }
        cp_wait<0>();
        __syncthreads();

        // ---- S = Q @ K^T
        float s[8][4];
#pragma unroll
        for (int n = 0; n < 8; n++)
#pragma unroll
            for (int j = 0; j < 4; j++) s[n][j] = 0.0f;
#pragma unroll
        for (int kk = 0; kk < 4; kk++) {
            int p = kk * 8 + lr;
#pragma unroll
            for (int n = 0; n < 8; n++) {
                int krow = n * 8 + lq;
                unsigned bh0 = KH[krow * AT_SK + p];
                unsigned bh1 = KH[krow * AT_SK + p + 4];
                unsigned bl0 = KL[krow * AT_SK + p];
                unsigned bl1 = KL[krow * AT_SK + p + 4];
                mma_bf16(s[n], qh[kk], bh0, bh1);
                mma_bf16(s[n], qh[kk], bl0, bl1);
                mma_bf16(s[n], ql[kk], bh0, bh1);
            }
        }

        // ---- causal mask (diagonal tile only)
        if (kt == qt) {
            int qr0 = w * 16 + lq;
#pragma unroll
            for (int n = 0; n < 8; n++) {
                int kc = n * 8 + 2 * lr;
                if (kc     > qr0)     s[n][0] = -1e30f;
                if (kc + 1 > qr0)     s[n][1] = -1e30f;
                if (kc     > qr0 + 8) s[n][2] = -1e30f;
                if (kc + 1 > qr0 + 8) s[n][3] = -1e30f;
            }
        }

        // ---- online softmax
        float rm0 = -1e30f, rm1 = -1e30f;
#pragma unroll
        for (int n = 0; n < 8; n++) {
            rm0 = fmaxf(rm0, fmaxf(s[n][0], s[n][1]));
            rm1 = fmaxf(rm1, fmaxf(s[n][2], s[n][3]));
        }
        rm0 = fmaxf(rm0, __shfl_xor_sync(0xffffffffu, rm0, 1));
        rm0 = fmaxf(rm0, __shfl_xor_sync(0xffffffffu, rm0, 2));
        rm1 = fmaxf(rm1, __shfl_xor_sync(0xffffffffu, rm1, 1));
        rm1 = fmaxf(rm1, __shfl_xor_sync(0xffffffffu, rm1, 2));
        float mn0 = fmaxf(m0, rm0), mn1 = fmaxf(m1, rm1);
        float c0 = __expf(m0 - mn0), c1 = __expf(m1 - mn1);
        m0 = mn0; m1 = mn1;

        int r0 = w * 16 + lq;
        float ps0 = 0.0f, ps1 = 0.0f;
#pragma unroll
        for (int n = 0; n < 8; n++) {
            float p00 = __expf(s[n][0] - mn0);
            float p01 = __expf(s[n][1] - mn0);
            float p10 = __expf(s[n][2] - mn1);
            float p11 = __expf(s[n][3] - mn1);
            ps0 += p00 + p01;
            ps1 += p10 + p11;
            unsigned hi, lo;
            split2(p00, p01, hi, lo);
            PH[r0 * AT_SK + n * 4 + lr] = hi;
            PL[r0 * AT_SK + n * 4 + lr] = lo;
            split2(p10, p11, hi, lo);
            PH[(r0 + 8) * AT_SK + n * 4 + lr] = hi;
            PL[(r0 + 8) * AT_SK + n * 4 + lr] = lo;
        }
        l0 = l0 * c0 + ps0;
        l1 = l1 * c1 + ps1;
#pragma unroll
        for (int n = 0; n < 8; n++) {
            o_acc[n][0] *= c0; o_acc[n][1] *= c0;
            o_acc[n][2] *= c1; o_acc[n][3] *= c1;
        }
        __syncwarp();

        // ---- O += P @ V
#pragma unroll
        for (int kk = 0; kk < 4; kk++) {
            int p = kk * 8 + lr;
            unsigned ah[4], al[4];
            ah[0] = PH[r0 * AT_SK + p];
            ah[1] = PH[(r0 + 8) * AT_SK + p];
            ah[2] = PH[r0 * AT_SK + p + 4];
            ah[3] = PH[(r0 + 8) * AT_SK + p + 4];
            al[0] = PL[r0 * AT_SK + p];
            al[1] = PL[(r0 + 8) * AT_SK + p];
            al[2] = PL[r0 * AT_SK + p + 4];
            al[3] = PL[(r0 + 8) * AT_SK + p + 4];
#pragma unroll
            for (int n = 0; n < 8; n++) {
                unsigned bh0 = VH[(kk * 8 + lr) * AT_SV + n * 8 + lq];
                unsigned bh1 = VH[(kk * 8 + lr + 4) * AT_SV + n * 8 + lq];
                unsigned bl0 = VL[(kk * 8 + lr) * AT_SV + n * 8 + lq];
                unsigned bl1 = VL[(kk * 8 + lr + 4) * AT_SV + n * 8 + lq];
                mma_bf16(o_acc[n], ah, bh0, bh1);
                mma_bf16(o_acc[n], ah, bl0, bl1);
                mma_bf16(o_acc[n], al, bh0, bh1);
            }
        }
        __syncwarp();
    }

    // ---- finalize: normalize and emit out-proj A planes
    l0 += __shfl_xor_sync(0xffffffffu, l0, 1);
    l0 += __shfl_xor_sync(0xffffffffu, l0, 2);
    l1 += __shfl_xor_sync(0xffffffffu, l1, 1);
    l1 += __shfl_xor_sync(0xffffffffu, l1, 2);
    float inv0 = 1.0f / l0, inv1 = 1.0f / l1;

    int row0 = b * T_SEQ + qt * 64 + w * 16 + lq;
#pragma unroll
    for (int n = 0; n < 8; n++) {
        int dp = h * 32 + n * 4 + lr;   // D-pair index
        unsigned hh, ll;
        split2(o_acc[n][0] * inv0, o_acc[n][1] * inv0, hh, ll);
        g_ah[(size_t)row0 * KP_MODEL + dp] = hh;
        g_al[(size_t)row0 * KP_MODEL + dp] = ll;
        split2(o_acc[n][2] * inv1, o_acc[n][3] * inv1, hh, ll);
        g_ah[(size_t)(row0 + 8) * KP_MODEL + dp] = hh;
        g_al[(size_t)(row0 + 8) * KP_MODEL + dp] = ll;
    }
}

// ---------------------------------------------------------------------------
extern "C" void kernel_launch(void* const* d_in, const int* in_sizes, int n_in,
                              void* d_out, int out_size)
{
    const float* x    = (const float*)d_in[0];
    const float* Wqkv = (const float*)d_in[1];
    const float* bqkv = (const float*)d_in[2];
    const float* Wo   = (const float*)d_in[3];
    const float* bo   = (const float*)d_in[4];
    float* out = (float*)d_out;

    unsigned *xh, *xl, *wqh, *wql, *woh, *wol, *ah, *al;
    cudaGetSymbolAddress((void**)&xh,  g_xh);
    cudaGetSymbolAddress((void**)&xl,  g_xl);
    cudaGetSymbolAddress((void**)&wqh, g_wqh);
    cudaGetSymbolAddress((void**)&wql, g_wql);
    cudaGetSymbolAddress((void**)&woh, g_woh);
    cudaGetSymbolAddress((void**)&wol, g_wol);
    cudaGetSymbolAddress((void**)&ah,  g_ah);
    cudaGetSymbolAddress((void**)&al,  g_al);

    cudaFuncSetAttribute(gemm_planes<0>, cudaFuncAttributeMaxDynamicSharedMemorySize, GEMM_SMEM);
    cudaFuncSetAttribute(gemm_planes<1>, cudaFuncAttributeMaxDynamicSharedMemorySize, GEMM_SMEM);
    cudaFuncSetAttribute(attn_tc, cudaFuncAttributeMaxDynamicSharedMemorySize, ATTN_SMEM);

    // 0) one-time splits
    {
        int tx = M_TOK * KP_MODEL;
        split_rowpairs<<<(tx + 255) / 256, 256>>>(x, xh, xl, tx);
        int tq = KP_MODEL * N_QKV;
        split_colpairs<<<(tq + 255) / 256, 256>>>(Wqkv, wqh, wql, N_QKV, tq);
        int to = KP_MODEL * D_MODEL;
        split_colpairs<<<(to + 255) / 256, 256>>>(Wo, woh, wol, D_MODEL, to);
    }

    // 1) QKV projection -> head-major split planes
    gemm_planes<1><<<dim3(N_QKV / 128, M_TOK / 128), 256, GEMM_SMEM>>>(
        xh, xl, wqh, wql, bqkv, nullptr, M_TOK, N_QKV, D_MODEL);

    // 2) causal flash attention -> out-proj A planes
    attn_tc<<<dim3(T_SEQ / 64, N_HEADS, B_SZ), 128, ATTN_SMEM>>>();

    // 3) output projection -> fp32 out
    gemm_planes<0><<<dim3(D_MODEL / 128, M_TOK / 128), 256, GEMM_SMEM>>>(
        ah, al, woh, wol, bo, out, M_TOK, D_MODEL, D_MODEL);
}

// round 5
// speedup vs baseline: 1.0562x; 1.0562x over previous
#include <cuda_runtime.h>
#include <cuda_bf16.h>

#define D_MODEL 768
#define KP_MODEL 384            // D/2 (u32 pairs)
#define N_HEADS 12
#define HD      64
#define B_SZ    4
#define T_SEQ   2048
#define M_TOK   (B_SZ * T_SEQ)  // 8192
#define N_QKV   (3 * D_MODEL)   // 2304

// ---------------- static device scratch (hi/lo bf16-pair planes, u32) -------
__device__ unsigned g_xh[(size_t)M_TOK * KP_MODEL],  g_xl[(size_t)M_TOK * KP_MODEL];
__device__ unsigned g_wqh[(size_t)KP_MODEL * N_QKV], g_wql[(size_t)KP_MODEL * N_QKV];
__device__ unsigned g_woh[(size_t)KP_MODEL * D_MODEL], g_wol[(size_t)KP_MODEL * D_MODEL];
// head-major [B][H][T][32] pair planes
#define HM_SZ ((size_t)B_SZ * N_HEADS * T_SEQ * 32)
__device__ unsigned g_qh[HM_SZ], g_ql[HM_SZ];
__device__ unsigned g_kh[HM_SZ], g_kl[HM_SZ];
__device__ unsigned g_vh[HM_SZ], g_vl[HM_SZ];
// attention output planes (A-operand layout for out-proj)
__device__ unsigned g_ah[(size_t)M_TOK * KP_MODEL], g_al[(size_t)M_TOK * KP_MODEL];

// ---------------------------------------------------------------------------
__device__ __forceinline__ void mma_bf16(float c[4], const unsigned a[4],
                                         unsigned b0, unsigned b1)
{
    asm volatile(
        "mma.sync.aligned.m16n8k16.row.col.f32.bf16.bf16.f32 "
        "{%0,%1,%2,%3}, {%4,%5,%6,%7}, {%8,%9}, {%0,%1,%2,%3};\n"
        : "+f"(c[0]), "+f"(c[1]), "+f"(c[2]), "+f"(c[3])
        : "r"(a[0]), "r"(a[1]), "r"(a[2]), "r"(a[3]), "r"(b0), "r"(b1));
}

__device__ __forceinline__ unsigned pack_bf2(float e_lo, float e_hi)
{
    __nv_bfloat162 t = __floats2bfloat162_rn(e_lo, e_hi); // .x -> low half
    return *reinterpret_cast<unsigned*>(&t);
}

__device__ __forceinline__ void split2(float x0, float x1, unsigned& hi, unsigned& lo)
{
    float h0 = __bfloat162float(__float2bfloat16(x0));
    float h1 = __bfloat162float(__float2bfloat16(x1));
    hi = pack_bf2(h0, h1);
    lo = pack_bf2(x0 - h0, x1 - h1);
}

__device__ __forceinline__ void cp16(unsigned* dst_smem, const unsigned* src)
{
    unsigned saddr = (unsigned)__cvta_generic_to_shared(dst_smem);
    asm volatile("cp.async.cg.shared.global [%0], [%1], 16;\n" :: "r"(saddr), "l"(src));
}
__device__ __forceinline__ void cp_commit() { asm volatile("cp.async.commit_group;\n"); }
template <int N>
__device__ __forceinline__ void cp_wait() { asm volatile("cp.async.wait_group %0;\n" :: "n"(N)); }

// ---------------------------------------------------------------------------
// Split kernels (run once per launch; memory-bound, tiny)
// ---------------------------------------------------------------------------
__global__ void split_rowpairs(const float* __restrict__ src,
                               unsigned* __restrict__ H, unsigned* __restrict__ L,
                               int total)
{
    int i = blockIdx.x * blockDim.x + threadIdx.x;
    if (i < total) {
        float2 v = ((const float2*)src)[i];
        unsigned h, l;
        split2(v.x, v.y, h, l);
        H[i] = h; L[i] = l;
    }
}

__global__ void split_colpairs(const float* __restrict__ src,
                               unsigned* __restrict__ H, unsigned* __restrict__ L,
                               int N, int total)
{
    int i = blockIdx.x * blockDim.x + threadIdx.x;
    if (i < total) {
        int kp = i / N, n = i - kp * N;
        float a = src[(size_t)(2 * kp) * N + n];
        float b = src[(size_t)(2 * kp + 1) * N + n];
        unsigned h, l;
        split2(a, b, h, l);
        H[i] = h; L[i] = l;
    }
}

// ---------------------------------------------------------------------------
// GEMM on pre-split planes. C[M,N] = A @ B (+bias).
// 128 thr = 4 warps (2x2), block tile 128x128, WARP TILE 64x64, BK=32,
// cp.async double-buffered. EPI=0: fp32 out. EPI=1: QKV -> head-major planes.
// ---------------------------------------------------------------------------
#define GA_STR 20
#define GB_STR 136
#define GA_SZ  (128 * GA_STR)           // 2560 u32
#define GB_SZ  (16 * GB_STR)            // 2176 u32
#define GBUF   (2 * GA_SZ + 2 * GB_SZ)  // 9472 u32
#define GEMM_SMEM (2 * GBUF * 4)        // 75776 bytes

template <int EPI>
__global__ __launch_bounds__(128) void gemm_planes(
    const unsigned* __restrict__ Ah, const unsigned* __restrict__ Al,
    const unsigned* __restrict__ Bh, const unsigned* __restrict__ Bl,
    const float* __restrict__ bias, float* __restrict__ Cout,
    int M, int N, int K)
{
    extern __shared__ unsigned sm[];
    const int tid  = threadIdx.x;
    const int lane = tid & 31;
    const int wid  = tid >> 5;
    const int wm   = wid >> 1;      // 0..1 -> 64-row slabs
    const int wn   = wid & 1;       // 0..1 -> 64-col slabs
    const int lq   = lane >> 2;
    const int lr   = lane & 3;
    const int bm = blockIdx.y, bn = blockIdx.x;
    const int KP = K >> 1;

    float acc[4][8][4];
#pragma unroll
    for (int mt = 0; mt < 4; mt++)
#pragma unroll
        for (int n = 0; n < 8; n++)
#pragma unroll
            for (int j = 0; j < 4; j++) acc[mt][n][j] = 0.0f;

    auto load_tile = [&](int kt, int buf) {
        unsigned* AHs = sm + buf * GBUF;
        unsigned* ALs = AHs + GA_SZ;
        unsigned* BHs = ALs + GA_SZ;
        unsigned* BLs = BHs + GB_SZ;
        const int kp0 = kt * 16;
#pragma unroll
        for (int i = 0; i < 4; i++) {
            int idx = tid + i * 128;          // 512 chunks: 128 rows x 4
            int row = idx >> 2, c4 = (idx & 3) * 4;
            size_t g = (size_t)(bm * 128 + row) * KP + kp0 + c4;
            cp16(&AHs[row * GA_STR + c4], Ah + g);
            cp16(&ALs[row * GA_STR + c4], Al + g);
        }
#pragma unroll
        for (int i = 0; i < 4; i++) {
            int idx = tid + i * 128;          // 512 chunks: 16 rows x 32
            int row = idx >> 5, c4 = (idx & 31) * 4;
            size_t g = (size_t)(kp0 + row) * N + bn * 128 + c4;
            cp16(&BHs[row * GB_STR + c4], Bh + g);
            cp16(&BLs[row * GB_STR + c4], Bl + g);
        }
    };

    const int KT = K / 32;
    load_tile(0, 0);
    cp_commit();

    for (int kt = 0; kt < KT; kt++) {
        int buf = kt & 1;
        if (kt + 1 < KT) {
            load_tile(kt + 1, buf ^ 1);
            cp_commit();
            cp_wait<1>();
        } else {
            cp_wait<0>();
        }
        __syncthreads();

        unsigned* AHs = sm + buf * GBUF;
        unsigned* ALs = AHs + GA_SZ;
        unsigned* BHs = ALs + GA_SZ;
        unsigned* BLs = BHs + GB_SZ;

#pragma unroll
        for (int kk = 0; kk < 2; kk++) {
            unsigned ah[4][4], al[4][4];
            const int p = kk * 8 + lr;
#pragma unroll
            for (int mt = 0; mt < 4; mt++) {
                int r = wm * 64 + mt * 16 + lq;
                ah[mt][0] = AHs[r * GA_STR + p];
                ah[mt][1] = AHs[(r + 8) * GA_STR + p];
                ah[mt][2] = AHs[r * GA_STR + p + 4];
                ah[mt][3] = AHs[(r + 8) * GA_STR + p + 4];
                al[mt][0] = ALs[r * GA_STR + p];
                al[mt][1] = ALs[(r + 8) * GA_STR + p];
                al[mt][2] = ALs[r * GA_STR + p + 4];
                al[mt][3] = ALs[(r + 8) * GA_STR + p + 4];
            }
#pragma unroll
            for (int n = 0; n < 8; n++) {
                int col = wn * 64 + n * 8 + lq;
                unsigned bh0 = BHs[p * GB_STR + col];
                unsigned bh1 = BHs[(p + 4) * GB_STR + col];
                unsigned bl0 = BLs[p * GB_STR + col];
                unsigned bl1 = BLs[(p + 4) * GB_STR + col];
#pragma unroll
                for (int mt = 0; mt < 4; mt++) {
                    mma_bf16(acc[mt][n], ah[mt], bh0, bh1);
                    mma_bf16(acc[mt][n], ah[mt], bl0, bl1);
                    mma_bf16(acc[mt][n], al[mt], bh0, bh1);
                }
            }
        }
        __syncthreads();
    }

    // ---- epilogue
#pragma unroll
    for (int mt = 0; mt < 4; mt++) {
        int row0 = bm * 128 + wm * 64 + mt * 16 + lq;
#pragma unroll
        for (int n = 0; n < 8; n++) {
            int col = bn * 128 + wn * 64 + n * 8 + 2 * lr;
            float b0 = bias[col], b1 = bias[col + 1];
            float x0 = acc[mt][n][0] + b0, x1 = acc[mt][n][1] + b1;
            float y0 = acc[mt][n][2] + b0, y1 = acc[mt][n][3] + b1;
            if (EPI == 0) {
                *(float2*)&Cout[(size_t)row0 * N + col]       = make_float2(x0, x1);
                *(float2*)&Cout[(size_t)(row0 + 8) * N + col] = make_float2(y0, y1);
            } else {
                int seg = col / D_MODEL;
                int nn  = col - seg * D_MODEL;
                int hh2 = nn >> 6;
                int dp  = (nn & 63) >> 1;
                if (seg == 0) { x0 *= 0.125f; x1 *= 0.125f; y0 *= 0.125f; y1 *= 0.125f; }
                unsigned* H = (seg == 0) ? g_qh : (seg == 1) ? g_kh : g_vh;
                unsigned* L = (seg == 0) ? g_ql : (seg == 1) ? g_kl : g_vl;
                int bb = row0 >> 11, t = row0 & 2047;
                size_t o = ((size_t)(bb * N_HEADS + hh2) * T_SEQ + t) * 32 + dp;
                unsigned hv, lv;
                split2(x0, x1, hv, lv);
                H[o] = hv; L[o] = lv;
                split2(y0, y1, hv, lv);
                H[o + 8 * 32] = hv; L[o + 8 * 32] = lv;
            }
        }
    }
}

// ---------------------------------------------------------------------------
// Flash attention (causal), split-bf16 tensor cores, 128-query tiles.
// 128 thr = 4 warps; warp w owns q rows [w*32, w*32+32) (2 m16 tiles).
// Q staged once in smem; K/V tiles of 64 keys per iteration.
// Smem (u32): QH/QL[128][36] KH/KL[64][36] VH/VL[32][72] PH/PL[128][36]
// ---------------------------------------------------------------------------
#define AT_SQ 36
#define AT_SK 36
#define AT_SV 72
#define ATTN_SMEM ((2*128*AT_SQ + 2*64*AT_SK + 2*32*AT_SV + 2*128*AT_SQ) * 4)  // 110592

__global__ __launch_bounds__(128) void attn_tc()
{
    extern __shared__ unsigned usm[];
    unsigned* QH = usm;
    unsigned* QL = QH + 128 * AT_SQ;
    unsigned* KH = QL + 128 * AT_SQ;
    unsigned* KL = KH + 64 * AT_SK;
    unsigned* VH = KL + 64 * AT_SK;
    unsigned* VL = VH + 32 * AT_SV;
    unsigned* PH = VL + 32 * AT_SV;
    unsigned* PL = PH + 128 * AT_SQ;

    const int b = blockIdx.z, h = blockIdx.y;
    const int qt = gridDim.x - 1 - blockIdx.x;      // heavy tiles first
    const int tid = threadIdx.x;
    const int w = tid >> 5, lane = tid & 31;
    const int lq = lane >> 2, lr = lane & 3;
    const size_t bh_base = (size_t)(b * N_HEADS + h) * T_SEQ * 32;

    // ---- stage Q tile (128 rows) once
    {
        const unsigned* Qgh = g_qh + bh_base + (size_t)qt * 128 * 32;
        const unsigned* Qgl = g_ql + bh_base + (size_t)qt * 128 * 32;
#pragma unroll
        for (int i = 0; i < 8; i++) {
            int idx = tid + i * 128;                // 1024 chunks: 128 rows x 8
            int row = idx >> 3, c4 = (idx & 7) * 4;
            cp16(&QH[row * AT_SQ + c4], Qgh + row * 32 + c4);
            cp16(&QL[row * AT_SQ + c4], Qgl + row * 32 + c4);
        }
        cp_commit();
        cp_wait<0>();
    }
    __syncthreads();

    float o_acc[2][8][4];
#pragma unroll
    for (int mt = 0; mt < 2; mt++)
#pragma unroll
        for (int n = 0; n < 8; n++)
#pragma unroll
            for (int j = 0; j < 4; j++) o_acc[mt][n][j] = 0.0f;
    float mrow[2][2] = {{-1e30f, -1e30f}, {-1e30f, -1e30f}};
    float lrow[2][2] = {{0.0f, 0.0f}, {0.0f, 0.0f}};

    const int kt_end = 2 * qt + 1;
    for (int kt = 0; kt <= kt_end; kt++) {
        __syncthreads();
        // K tile: raw cp.async copy of contiguous planes
        {
            const unsigned* Kgh = g_kh + bh_base + (size_t)kt * 64 * 32;
            const unsigned* Kgl = g_kl + bh_base + (size_t)kt * 64 * 32;
#pragma unroll
            for (int i = 0; i < 4; i++) {
                int idx = tid + i * 128;            // 512 chunks: 64 rows x 8
                int row = idx >> 3, c4 = (idx & 7) * 4;
                cp16(&KH[row * AT_SK + c4], Kgh + row * 32 + c4);
                cp16(&KL[row * AT_SK + c4], Kgl + row * 32 + c4);
            }
            cp_commit();
        }
        // V tile: repack d-pairs -> key-pairs with PRMT (overlaps K cp.async)
        {
            const unsigned* Vgh = g_vh + bh_base + (size_t)kt * 64 * 32;
            const unsigned* Vgl = g_vl + bh_base + (size_t)kt * 64 * 32;
#pragma unroll
            for (int i = 0; i < 2; i++) {
                int idx = tid + i * 128;            // 256: 32 kp x 8 jb
                int kp = idx >> 3, jb = (idx & 7) * 4;
                uint4 a = *(const uint4*)(Vgh + (2 * kp) * 32 + jb);
                uint4 c = *(const uint4*)(Vgh + (2 * kp + 1) * 32 + jb);
                uint4 o0, o1;
                o0.x = __byte_perm(a.x, c.x, 0x5410); o0.y = __byte_perm(a.x, c.x, 0x7632);
                o0.z = __byte_perm(a.y, c.y, 0x5410); o0.w = __byte_perm(a.y, c.y, 0x7632);
                o1.x = __byte_perm(a.z, c.z, 0x5410); o1.y = __byte_perm(a.z, c.z, 0x7632);
                o1.z = __byte_perm(a.w, c.w, 0x5410); o1.w = __byte_perm(a.w, c.w, 0x7632);
                *(uint4*)&VH[kp * AT_SV + 2 * jb]     = o0;
                *(uint4*)&VH[kp * AT_SV + 2 * jb + 4] = o1;
                a = *(const uint4*)(Vgl + (2 * kp) * 32 + jb);
                c = *(const uint4*)(Vgl + (2 * kp + 1) * 32 + jb);
                o0.x = __byte_perm(a.x, c.x, 0x5410); o0.y = __byte_perm(a.x, c.x, 0x7632);
                o0.z = __byte_perm(a.y, c.y, 0x5410); o0.w = __byte_perm(a.y, c.y, 0x7632);
                o1.x = __byte_perm(a.z, c.z, 0x5410); o1.y = __byte_perm(a.z, c.z, 0x7632);
                o1.z = __byte_perm(a.w, c.w, 0x5410); o1.w = __byte_perm(a.w, c.w, 0x7632);
                *(uint4*)&VL[kp * AT_SV + 2 * jb]     = o0;
                *(uint4*)&VL[kp * AT_SV + 2 * jb + 4] = o1;
            }
        }
        cp_wait<0>();
        __syncthreads();

        // warps whose rows are entirely below this key tile skip compute
        const bool active = (kt * 64 <= qt * 128 + w * 32 + 31);
        if (active) {
            // ---- S = Q @ K^T
            float s[2][8][4];
#pragma unroll
            for (int mt = 0; mt < 2; mt++)
#pragma unroll
                for (int n = 0; n < 8; n++)
#pragma unroll
                    for (int j = 0; j < 4; j++) s[mt][n][j] = 0.0f;
#pragma unroll
            for (int kk = 0; kk < 4; kk++) {
                const int p = kk * 8 + lr;
                unsigned qhf[2][4], qlf[2][4];
#pragma unroll
                for (int mt = 0; mt < 2; mt++) {
                    int r0 = w * 32 + mt * 16 + lq;
                    qhf[mt][0] = QH[r0 * AT_SQ + p];
                    qhf[mt][1] = QH[(r0 + 8) * AT_SQ + p];
                    qhf[mt][2] = QH[r0 * AT_SQ + p + 4];
                    qhf[mt][3] = QH[(r0 + 8) * AT_SQ + p + 4];
                    qlf[mt][0] = QL[r0 * AT_SQ + p];
                    qlf[mt][1] = QL[(r0 + 8) * AT_SQ + p];
                    qlf[mt][2] = QL[r0 * AT_SQ + p + 4];
                    qlf[mt][3] = QL[(r0 + 8) * AT_SQ + p + 4];
                }
#pragma unroll
                for (int n = 0; n < 8; n++) {
                    int krow = n * 8 + lq;
                    unsigned bh0 = KH[krow * AT_SK + p];
                    unsigned bh1 = KH[krow * AT_SK + p + 4];
                    unsigned bl0 = KL[krow * AT_SK + p];
                    unsigned bl1 = KL[krow * AT_SK + p + 4];
#pragma unroll
                    for (int mt = 0; mt < 2; mt++) {
                        mma_bf16(s[mt][n], qhf[mt], bh0, bh1);
                        mma_bf16(s[mt][n], qhf[mt], bl0, bl1);
                        mma_bf16(s[mt][n], qlf[mt], bh0, bh1);
                    }
                }
            }

            // ---- causal mask (only tiles that touch the diagonal)
            if ((kt + 1) * 64 > qt * 128 + w * 32) {
#pragma unroll
                for (int mt = 0; mt < 2; mt++) {
                    int qr0 = qt * 128 + w * 32 + mt * 16 + lq;
#pragma unroll
                    for (int n = 0; n < 8; n++) {
                        int kc = kt * 64 + n * 8 + 2 * lr;
                        if (kc     > qr0)     s[mt][n][0] = -1e30f;
                        if (kc + 1 > qr0)     s[mt][n][1] = -1e30f;
                        if (kc     > qr0 + 8) s[mt][n][2] = -1e30f;
                        if (kc + 1 > qr0 + 8) s[mt][n][3] = -1e30f;
                    }
                }
            }

            // ---- online softmax per m16 tile
#pragma unroll
            for (int mt = 0; mt < 2; mt++) {
                float rm0 = -1e30f, rm1 = -1e30f;
#pragma unroll
                for (int n = 0; n < 8; n++) {
                    rm0 = fmaxf(rm0, fmaxf(s[mt][n][0], s[mt][n][1]));
                    rm1 = fmaxf(rm1, fmaxf(s[mt][n][2], s[mt][n][3]));
                }
                rm0 = fmaxf(rm0, __shfl_xor_sync(0xffffffffu, rm0, 1));
                rm0 = fmaxf(rm0, __shfl_xor_sync(0xffffffffu, rm0, 2));
                rm1 = fmaxf(rm1, __shfl_xor_sync(0xffffffffu, rm1, 1));
                rm1 = fmaxf(rm1, __shfl_xor_sync(0xffffffffu, rm1, 2));
                float mn0 = fmaxf(mrow[mt][0], rm0), mn1 = fmaxf(mrow[mt][1], rm1);
                float c0 = __expf(mrow[mt][0] - mn0), c1 = __expf(mrow[mt][1] - mn1);
                mrow[mt][0] = mn0; mrow[mt][1] = mn1;

                int r0 = w * 32 + mt * 16 + lq;
                float ps0 = 0.0f, ps1 = 0.0f;
#pragma unroll
                for (int n = 0; n < 8; n++) {
                    float p00 = __expf(s[mt][n][0] - mn0);
                    float p01 = __expf(s[mt][n][1] - mn0);
                    float p10 = __expf(s[mt][n][2] - mn1);
                    float p11 = __expf(s[mt][n][3] - mn1);
                    ps0 += p00 + p01;
                    ps1 += p10 + p11;
                    unsigned hv, lv;
                    split2(p00, p01, hv, lv);
                    PH[r0 * AT_SQ + n * 4 + lr] = hv;
                    PL[r0 * AT_SQ + n * 4 + lr] = lv;
                    split2(p10, p11, hv, lv);
                    PH[(r0 + 8) * AT_SQ + n * 4 + lr] = hv;
                    PL[(r0 + 8) * AT_SQ + n * 4 + lr] = lv;
                }
                lrow[mt][0] = lrow[mt][0] * c0 + ps0;
                lrow[mt][1] = lrow[mt][1] * c1 + ps1;
#pragma unroll
                for (int n = 0; n < 8; n++) {
                    o_acc[mt][n][0] *= c0; o_acc[mt][n][1] *= c0;
                    o_acc[mt][n][2] *= c1; o_acc[mt][n][3] *= c1;
                }
            }
            __syncwarp();

            // ---- O += P @ V
#pragma unroll
            for (int kk = 0; kk < 4; kk++) {
                const int p = kk * 8 + lr;
                unsigned ahf[2][4], alf[2][4];
#pragma unroll
                for (int mt = 0; mt < 2; mt++) {
                    int r0 = w * 32 + mt * 16 + lq;
                    ahf[mt][0] = PH[r0 * AT_SQ + p];
                    ahf[mt][1] = PH[(r0 + 8) * AT_SQ + p];
                    ahf[mt][2] = PH[r0 * AT_SQ + p + 4];
                    ahf[mt][3] = PH[(r0 + 8) * AT_SQ + p + 4];
                    alf[mt][0] = PL[r0 * AT_SQ + p];
                    alf[mt][1] = PL[(r0 + 8) * AT_SQ + p];
                    alf[mt][2] = PL[r0 * AT_SQ + p + 4];
                    alf[mt][3] = PL[(r0 + 8) * AT_SQ + p + 4];
                }
#pragma unroll
                for (int n = 0; n < 8; n++) {
                    unsigned bh0 = VH[p * AT_SV + n * 8 + lq];
                    unsigned bh1 = VH[(p + 4) * AT_SV + n * 8 + lq];
                    unsigned bl0 = VL[p * AT_SV + n * 8 + lq];
                    unsigned bl1 = VL[(p + 4) * AT_SV + n * 8 + lq];
#pragma unroll
                    for (int mt = 0; mt < 2; mt++) {
                        mma_bf16(o_acc[mt][n], ahf[mt], bh0, bh1);
                        mma_bf16(o_acc[mt][n], ahf[mt], bl0, bl1);
                        mma_bf16(o_acc[mt][n], alf[mt], bh0, bh1);
                    }
                }
            }
            __syncwarp();
        }
    }

    // ---- finalize: normalize and emit out-proj A planes
#pragma unroll
    for (int mt = 0; mt < 2; mt++) {
        float l0 = lrow[mt][0], l1 = lrow[mt][1];
        l0 += __shfl_xor_sync(0xffffffffu, l0, 1);
        l0 += __shfl_xor_sync(0xffffffffu, l0, 2);
        l1 += __shfl_xor_sync(0xffffffffu, l1, 1);
        l1 += __shfl_xor_sync(0xffffffffu, l1, 2);
        float inv0 = 1.0f / l0, inv1 = 1.0f / l1;

        int row0 = b * T_SEQ + qt * 128 + w * 32 + mt * 16 + lq;
#pragma unroll
        for (int n = 0; n < 8; n++) {
            int dp = h * 32 + n * 4 + lr;
            unsigned hv, lv;
            split2(o_acc[mt][n][0] * inv0, o_acc[mt][n][1] * inv0, hv, lv);
            g_ah[(size_t)row0 * KP_MODEL + dp] = hv;
            g_al[(size_t)row0 * KP_MODEL + dp] = lv;
            split2(o_acc[mt][n][2] * inv1, o_acc[mt][n][3] * inv1, hv, lv);
            g_ah[(size_t)(row0 + 8) * KP_MODEL + dp] = hv;
            g_al[(size_t)(row0 + 8) * KP_MODEL + dp] = lv;
        }
    }
}

// ---------------------------------------------------------------------------
extern "C" void kernel_launch(void* const* d_in, const int* in_sizes, int n_in,
                              void* d_out, int out_size)
{
    const float* x    = (const float*)d_in[0];
    const float* Wqkv = (const float*)d_in[1];
    const float* bqkv = (const float*)d_in[2];
    const float* Wo   = (const float*)d_in[3];
    const float* bo   = (const float*)d_in[4];
    float* out = (float*)d_out;

    unsigned *xh, *xl, *wqh, *wql, *woh, *wol, *ah, *al;
    cudaGetSymbolAddress((void**)&xh,  g_xh);
    cudaGetSymbolAddress((void**)&xl,  g_xl);
    cudaGetSymbolAddress((void**)&wqh, g_wqh);
    cudaGetSymbolAddress((void**)&wql, g_wql);
    cudaGetSymbolAddress((void**)&woh, g_woh);
    cudaGetSymbolAddress((void**)&wol, g_wol);
    cudaGetSymbolAddress((void**)&ah,  g_ah);
    cudaGetSymbolAddress((void**)&al,  g_al);

    cudaFuncSetAttribute(gemm_planes<0>, cudaFuncAttributeMaxDynamicSharedMemorySize, GEMM_SMEM);
    cudaFuncSetAttribute(gemm_planes<1>, cudaFuncAttributeMaxDynamicSharedMemorySize, GEMM_SMEM);
    cudaFuncSetAttribute(attn_tc, cudaFuncAttributeMaxDynamicSharedMemorySize, ATTN_SMEM);

    // 0) one-time splits
    {
        int tx = M_TOK * KP_MODEL;
        split_rowpairs<<<(tx + 255) / 256, 256>>>(x, xh, xl, tx);
        int tq = KP_MODEL * N_QKV;
        split_colpairs<<<(tq + 255) / 256, 256>>>(Wqkv, wqh, wql, N_QKV, tq);
        int to = KP_MODEL * D_MODEL;
        split_colpairs<<<(to + 255) / 256, 256>>>(Wo, woh, wol, D_MODEL, to);
    }

    // 1) QKV projection -> head-major split planes
    gemm_planes<1><<<dim3(N_QKV / 128, M_TOK / 128), 128, GEMM_SMEM>>>(
        xh, xl, wqh, wql, bqkv, nullptr, M_TOK, N_QKV, D_MODEL);

    // 2) causal flash attention -> out-proj A planes
    attn_tc<<<dim3(T_SEQ / 128, N_HEADS, B_SZ), 128, ATTN_SMEM>>>();

    // 3) output projection -> fp32 out
    gemm_planes<0><<<dim3(D_MODEL / 128, M_TOK / 128), 128, GEMM_SMEM>>>(
        ah, al, woh, wol, bo, out, M_TOK, D_MODEL, D_MODEL);
}